// round 3
// baseline (speedup 1.0000x reference)
#include <cuda_runtime.h>

// Problem constants
#define BB 4
#define SS 2048
#define DD 512
#define HH 8
#define HDIM 64
#define MTOT (BB*SS)          // 8192 rows

// Scratch for projected q,k,v  (each 16.8 MB)
__device__ float g_q[BB*SS*DD];
__device__ float g_k[BB*SS*DD];
__device__ float g_v[BB*SS*DD];

// ---------------------------------------------------------------------------
// Kernel A: C = x @ W^T + b  for q,k,v  (blockIdx.z selects which)
// x: [M=8192, K=512] row-major;  W: [N=512, K=512] row-major (torch Linear)
// 128x128x16 tiles, 256 threads, 8x8 microtile.
// ---------------------------------------------------------------------------
#define BM 128
#define BN 128
#define BK 16

__global__ __launch_bounds__(256) void qkv_gemm_kernel(
    const float* __restrict__ x,
    const float* __restrict__ Wq, const float* __restrict__ bq,
    const float* __restrict__ Wk, const float* __restrict__ bk,
    const float* __restrict__ Wv, const float* __restrict__ bv)
{
    const float* W;
    const float* bias;
    float* out;
    if (blockIdx.z == 0)      { W = Wq; bias = bq; out = g_q; }
    else if (blockIdx.z == 1) { W = Wk; bias = bk; out = g_k; }
    else                      { W = Wv; bias = bv; out = g_v; }

    __shared__ float As[BK][BM];   // transposed: As[k][m]
    __shared__ float Bs[BK][BN];   // transposed: Bs[k][n]

    const int tid = threadIdx.x;
    const int tx = tid & 15;       // 0..15 -> N microtile
    const int ty = tid >> 4;       // 0..15 -> M microtile
    const int rowBase = blockIdx.y * BM;
    const int colBase = blockIdx.x * BN;

    float acc[8][8];
    #pragma unroll
    for (int i = 0; i < 8; i++)
        #pragma unroll
        for (int j = 0; j < 8; j++) acc[i][j] = 0.0f;

    for (int k0 = 0; k0 < DD; k0 += BK) {
        // Load A and B tiles (each 128x16 floats) with float4, store transposed.
        #pragma unroll
        for (int i = 0; i < 2; i++) {
            int f4 = tid + i * 256;       // 0..511
            int r  = f4 >> 2;             // 0..127
            int c4 = f4 & 3;              // 0..3  (group of 4 k-cols)
            float4 a = *(const float4*)&x[(size_t)(rowBase + r) * DD + k0 + c4 * 4];
            As[c4*4+0][r] = a.x; As[c4*4+1][r] = a.y;
            As[c4*4+2][r] = a.z; As[c4*4+3][r] = a.w;
            float4 w = *(const float4*)&W[(size_t)(colBase + r) * DD + k0 + c4 * 4];
            Bs[c4*4+0][r] = w.x; Bs[c4*4+1][r] = w.y;
            Bs[c4*4+2][r] = w.z; Bs[c4*4+3][r] = w.w;
        }
        __syncthreads();

        #pragma unroll
        for (int kk = 0; kk < BK; kk++) {
            float4 a0 = *(const float4*)&As[kk][ty * 8];
            float4 a1 = *(const float4*)&As[kk][ty * 8 + 4];
            float4 b0 = *(const float4*)&Bs[kk][tx * 8];
            float4 b1 = *(const float4*)&Bs[kk][tx * 8 + 4];
            float ar[8] = {a0.x, a0.y, a0.z, a0.w, a1.x, a1.y, a1.z, a1.w};
            float br[8] = {b0.x, b0.y, b0.z, b0.w, b1.x, b1.y, b1.z, b1.w};
            #pragma unroll
            for (int i = 0; i < 8; i++)
                #pragma unroll
                for (int j = 0; j < 8; j++)
                    acc[i][j] = fmaf(ar[i], br[j], acc[i][j]);
        }
        __syncthreads();
    }

    // Epilogue: add bias, store.
    const int colLo = colBase + tx * 8;
    float4 bv0 = *(const float4*)&bias[colLo];
    float4 bv1 = *(const float4*)&bias[colLo + 4];
    #pragma unroll
    for (int i = 0; i < 8; i++) {
        int row = rowBase + ty * 8 + i;
        float4 o0, o1;
        o0.x = acc[i][0] + bv0.x; o0.y = acc[i][1] + bv0.y;
        o0.z = acc[i][2] + bv0.z; o0.w = acc[i][3] + bv0.w;
        o1.x = acc[i][4] + bv1.x; o1.y = acc[i][5] + bv1.y;
        o1.z = acc[i][6] + bv1.z; o1.w = acc[i][7] + bv1.w;
        *(float4*)&out[(size_t)row * DD + colLo]     = o0;
        *(float4*)&out[(size_t)row * DD + colLo + 4] = o1;
    }
}

// ---------------------------------------------------------------------------
// Kernel B: flash attention, fp32.
// grid = (S/128, H, B); 128 threads; 1 thread = 1 query row.
// K/V tiles of 32 keys x 64 dims staged in smem.
// Softmax scale (1/sqrt(64) = 0.125) is folded into the q registers.
// ---------------------------------------------------------------------------
#define TK 32

__global__ __launch_bounds__(128) void attn_kernel(float* __restrict__ out)
{
    const int b = blockIdx.z;
    const int h = blockIdx.y;
    const int s = blockIdx.x * 128 + threadIdx.x;

    __shared__ float Ks[TK][HDIM];
    __shared__ float Vs[TK][HDIM];

    // Load this thread's query row into registers, pre-scaled by 1/sqrt(HD).
    const float* qptr = &g_q[((size_t)(b * SS + s)) * DD + h * HDIM];
    float q[HDIM];
    #pragma unroll
    for (int i = 0; i < HDIM / 4; i++) {
        float4 t = *(const float4*)&qptr[i * 4];
        q[i*4+0] = t.x * 0.125f; q[i*4+1] = t.y * 0.125f;
        q[i*4+2] = t.z * 0.125f; q[i*4+3] = t.w * 0.125f;
    }

    float O[HDIM];
    #pragma unroll
    for (int d = 0; d < HDIM; d++) O[d] = 0.0f;
    float m = -1e30f;
    float l = 0.0f;

    for (int kt = 0; kt < SS; kt += TK) {
        // Stage K and V tiles (2048 floats each) coalesced.
        #pragma unroll
        for (int i = 0; i < 4; i++) {
            int f4 = threadIdx.x + i * 128;   // 0..511
            int j  = f4 >> 4;                 // key row 0..31
            int d4 = f4 & 15;                 // float4 idx 0..15
            size_t base = ((size_t)(b * SS + kt + j)) * DD + h * HDIM + d4 * 4;
            *(float4*)&Ks[j][d4 * 4] = *(const float4*)&g_k[base];
            *(float4*)&Vs[j][d4 * 4] = *(const float4*)&g_v[base];
        }
        __syncthreads();

        // Scores for this tile.
        float sc[TK];
        float tmax = -1e30f;
        #pragma unroll
        for (int j = 0; j < TK; j++) {
            float a0 = 0.f, a1 = 0.f, a2 = 0.f, a3 = 0.f;
            #pragma unroll
            for (int d = 0; d < HDIM; d += 4) {
                float4 kv = *(const float4*)&Ks[j][d];
                a0 = fmaf(q[d+0], kv.x, a0);
                a1 = fmaf(q[d+1], kv.y, a1);
                a2 = fmaf(q[d+2], kv.z, a2);
                a3 = fmaf(q[d+3], kv.w, a3);
            }
            float v = (a0 + a1) + (a2 + a3);
            sc[j] = v;
            tmax = fmaxf(tmax, v);
        }

        // Online softmax update.
        float mnew  = fmaxf(m, tmax);
        float alpha = __expf(m - mnew);
        l *= alpha;
        #pragma unroll
        for (int d = 0; d < HDIM; d++) O[d] *= alpha;

        #pragma unroll
        for (int j = 0; j < TK; j++) {
            float p = __expf(sc[j] - mnew);
            l += p;
            #pragma unroll
            for (int d = 0; d < HDIM; d += 4) {
                float4 vv = *(const float4*)&Vs[j][d];
                O[d+0] = fmaf(p, vv.x, O[d+0]);
                O[d+1] = fmaf(p, vv.y, O[d+1]);
                O[d+2] = fmaf(p, vv.z, O[d+2]);
                O[d+3] = fmaf(p, vv.w, O[d+3]);
            }
        }
        m = mnew;
        __syncthreads();
    }

    // Write normalized output.
    const float inv = 1.0f / l;
    float* op = &out[((size_t)(b * SS + s)) * DD + h * HDIM];
    #pragma unroll
    for (int d = 0; d < HDIM; d += 4) {
        float4 t;
        t.x = O[d+0] * inv; t.y = O[d+1] * inv;
        t.z = O[d+2] * inv; t.w = O[d+3] * inv;
        *(float4*)&op[d] = t;
    }
}

// ---------------------------------------------------------------------------
extern "C" void kernel_launch(void* const* d_in, const int* in_sizes, int n_in,
                              void* d_out, int out_size)
{
    const float* x  = (const float*)d_in[0];
    const float* Wq = (const float*)d_in[1];
    const float* bq = (const float*)d_in[2];
    const float* Wk = (const float*)d_in[3];
    const float* bk = (const float*)d_in[4];
    const float* Wv = (const float*)d_in[5];
    const float* bv = (const float*)d_in[6];
    float* out = (float*)d_out;

    dim3 g1(DD / BN, MTOT / BM, 3);      // (4, 64, 3)
    qkv_gemm_kernel<<<g1, 256>>>(x, Wq, bq, Wk, bk, Wv, bv);

    dim3 g2(SS / 128, HH, BB);           // (16, 8, 4)
    attn_kernel<<<g2, 128>>>(out);
}

// round 6
// speedup vs baseline: 1.6054x; 1.6054x over previous
#include <cuda_runtime.h>
#include <cuda_bf16.h>
#include <cstdint>

// Problem constants
#define BB 4
#define SS 2048
#define DD 512
#define HH 8
#define HDIM 64
#define MTOT (BB*SS)          // 8192 rows

// Scratch for projected q,k,v  (each 16.8 MB)
__device__ float g_q[BB*SS*DD];
__device__ float g_k[BB*SS*DD];
__device__ float g_v[BB*SS*DD];

// ===========================================================================
// Helpers: bf16 split + packing + warp MMA (valid on base sm_100)
// ===========================================================================
__device__ __forceinline__ uint32_t pack_bf16(__nv_bfloat16 x, __nv_bfloat16 y) {
    return (uint32_t)__bfloat16_as_ushort(x) | ((uint32_t)__bfloat16_as_ushort(y) << 16);
}
// Split float2 into hi/lo bf16 pairs (x -> .lo16, y -> .hi16)
__device__ __forceinline__ void split2(float2 v, uint32_t& hi, uint32_t& lo) {
    __nv_bfloat16 hx = __float2bfloat16(v.x), hy = __float2bfloat16(v.y);
    float rx = v.x - __bfloat162float(hx);
    float ry = v.y - __bfloat162float(hy);
    hi = pack_bf16(hx, hy);
    lo = pack_bf16(__float2bfloat16(rx), __float2bfloat16(ry));
}
__device__ __forceinline__ void mma16816(float c[4], const uint32_t a[4],
                                         uint32_t b0, uint32_t b1) {
    asm volatile(
        "mma.sync.aligned.m16n8k16.row.col.f32.bf16.bf16.f32 "
        "{%0,%1,%2,%3}, {%4,%5,%6,%7}, {%8,%9}, {%0,%1,%2,%3};"
        : "+f"(c[0]), "+f"(c[1]), "+f"(c[2]), "+f"(c[3])
        : "r"(a[0]), "r"(a[1]), "r"(a[2]), "r"(a[3]), "r"(b0), "r"(b1));
}

// ===========================================================================
// Kernel A: QKV GEMM (validated fp32 FMA path)
// ===========================================================================
#define BM 128
#define BN 128
#define BK 16

__global__ __launch_bounds__(256) void qkv_gemm_kernel(
    const float* __restrict__ x,
    const float* __restrict__ Wq, const float* __restrict__ bq,
    const float* __restrict__ Wk, const float* __restrict__ bk,
    const float* __restrict__ Wv, const float* __restrict__ bv)
{
    const float* W;
    const float* bias;
    float* out;
    if (blockIdx.z == 0)      { W = Wq; bias = bq; out = g_q; }
    else if (blockIdx.z == 1) { W = Wk; bias = bk; out = g_k; }
    else                      { W = Wv; bias = bv; out = g_v; }

    __shared__ float As[BK][BM];
    __shared__ float Bs[BK][BN];

    const int tid = threadIdx.x;
    const int tx = tid & 15;
    const int ty = tid >> 4;
    const int rowBase = blockIdx.y * BM;
    const int colBase = blockIdx.x * BN;

    float acc[8][8];
    #pragma unroll
    for (int i = 0; i < 8; i++)
        #pragma unroll
        for (int j = 0; j < 8; j++) acc[i][j] = 0.0f;

    for (int k0 = 0; k0 < DD; k0 += BK) {
        #pragma unroll
        for (int i = 0; i < 2; i++) {
            int f4 = tid + i * 256;
            int r  = f4 >> 2;
            int c4 = f4 & 3;
            float4 a = *(const float4*)&x[(size_t)(rowBase + r) * DD + k0 + c4 * 4];
            As[c4*4+0][r] = a.x; As[c4*4+1][r] = a.y;
            As[c4*4+2][r] = a.z; As[c4*4+3][r] = a.w;
            float4 w = *(const float4*)&W[(size_t)(colBase + r) * DD + k0 + c4 * 4];
            Bs[c4*4+0][r] = w.x; Bs[c4*4+1][r] = w.y;
            Bs[c4*4+2][r] = w.z; Bs[c4*4+3][r] = w.w;
        }
        __syncthreads();

        #pragma unroll
        for (int kk = 0; kk < BK; kk++) {
            float4 a0 = *(const float4*)&As[kk][ty * 8];
            float4 a1 = *(const float4*)&As[kk][ty * 8 + 4];
            float4 b0 = *(const float4*)&Bs[kk][tx * 8];
            float4 b1 = *(const float4*)&Bs[kk][tx * 8 + 4];
            float ar[8] = {a0.x, a0.y, a0.z, a0.w, a1.x, a1.y, a1.z, a1.w};
            float br[8] = {b0.x, b0.y, b0.z, b0.w, b1.x, b1.y, b1.z, b1.w};
            #pragma unroll
            for (int i = 0; i < 8; i++)
                #pragma unroll
                for (int j = 0; j < 8; j++)
                    acc[i][j] = fmaf(ar[i], br[j], acc[i][j]);
        }
        __syncthreads();
    }

    const int colLo = colBase + tx * 8;
    float4 bv0 = *(const float4*)&bias[colLo];
    float4 bv1 = *(const float4*)&bias[colLo + 4];
    #pragma unroll
    for (int i = 0; i < 8; i++) {
        int row = rowBase + ty * 8 + i;
        float4 o0, o1;
        o0.x = acc[i][0] + bv0.x; o0.y = acc[i][1] + bv0.y;
        o0.z = acc[i][2] + bv0.z; o0.w = acc[i][3] + bv0.w;
        o1.x = acc[i][4] + bv1.x; o1.y = acc[i][5] + bv1.y;
        o1.z = acc[i][6] + bv1.z; o1.w = acc[i][7] + bv1.w;
        *(float4*)&out[(size_t)row * DD + colLo]     = o0;
        *(float4*)&out[(size_t)row * DD + colLo + 4] = o1;
    }
}

// ===========================================================================
// Kernel B: warp-MMA flash attention, split-bf16 (3-pass) fp32 emulation.
// grid = (S/64, H, B), 128 threads. Warp w owns query rows [w*16, w*16+16).
// K tile: 64 keys. K smem [key][dim] (pad 72). V smem transposed [dim][key]
// (pad 72, XOR swizzle on key to avoid store conflicts).
// Scores and P stay in registers (C-frag == A-frag layout).
// ===========================================================================
#define KT 64
#define NT (SS / KT)
#define PADR 72

__global__ __launch_bounds__(128) void attn_mma_kernel(float* __restrict__ out)
{
    __shared__ uint16_t Kh[KT * PADR];
    __shared__ uint16_t Kl[KT * PADR];
    __shared__ uint16_t Vh[HDIM * PADR];
    __shared__ uint16_t Vl[HDIM * PADR];

    const int tid  = threadIdx.x;
    const int w    = tid >> 5;
    const int lane = tid & 31;
    const int r0   = lane >> 2;        // row in 8-row group
    const int c0   = (lane & 3) * 2;   // column pair base
    const int qt = blockIdx.x, h = blockIdx.y, b = blockIdx.z;
    const int hb = h * HDIM;
    const int qr = qt * 64 + w * 16 + r0;   // this lane's first query row

    // ---- Q fragments (hi/lo), scaled by 1/sqrt(64)=0.125, loaded once ----
    uint32_t aQh[4][4], aQl[4][4];
    #pragma unroll
    for (int kc = 0; kc < 4; kc++) {
        const float s = 0.125f;
        float2 v;
        v = *(const float2*)&g_q[((size_t)(b*SS + qr    ))*DD + hb + kc*16 + c0    ];
        v.x *= s; v.y *= s; split2(v, aQh[kc][0], aQl[kc][0]);
        v = *(const float2*)&g_q[((size_t)(b*SS + qr + 8))*DD + hb + kc*16 + c0    ];
        v.x *= s; v.y *= s; split2(v, aQh[kc][1], aQl[kc][1]);
        v = *(const float2*)&g_q[((size_t)(b*SS + qr    ))*DD + hb + kc*16 + c0 + 8];
        v.x *= s; v.y *= s; split2(v, aQh[kc][2], aQl[kc][2]);
        v = *(const float2*)&g_q[((size_t)(b*SS + qr + 8))*DD + hb + kc*16 + c0 + 8];
        v.x *= s; v.y *= s; split2(v, aQh[kc][3], aQl[kc][3]);
    }

    float o[8][4];
    #pragma unroll
    for (int dt = 0; dt < 8; dt++)
        #pragma unroll
        for (int i = 0; i < 4; i++) o[dt][i] = 0.0f;
    float mA = -1e30f, mB = -1e30f, lA = 0.0f, lB = 0.0f;

    for (int t = 0; t < NT; t++) {
        if (t) __syncthreads();   // all warps done reading previous tiles

        // ---- Stage K (row-major) and V (transposed, swizzled) ----
        #pragma unroll
        for (int i = 0; i < 16; i++) {
            int p  = tid + i * 128;
            int kr = p >> 5;         // key 0..63
            int cp = p & 31;         // dim pair 0..31
            size_t base = ((size_t)(b*SS + t*KT + kr))*DD + hb + cp*2;
            uint32_t hi, lo;
            split2(*(const float2*)&g_k[base], hi, lo);
            *(uint32_t*)&Kh[kr*PADR + cp*2] = hi;
            *(uint32_t*)&Kl[kr*PADR + cp*2] = lo;

            float2 vv = *(const float2*)&g_v[base];
            __nv_bfloat16 hx = __float2bfloat16(vv.x), hy = __float2bfloat16(vv.y);
            int d0 = cp*2, d1 = cp*2 + 1;
            int k0s = kr ^ ((d0 & 3) << 4);
            int k1s = kr ^ ((d1 & 3) << 4);
            Vh[d0*PADR + k0s] = __bfloat16_as_ushort(hx);
            Vh[d1*PADR + k1s] = __bfloat16_as_ushort(hy);
            Vl[d0*PADR + k0s] = __bfloat16_as_ushort(__float2bfloat16(vv.x - __bfloat162float(hx)));
            Vl[d1*PADR + k1s] = __bfloat16_as_ushort(__float2bfloat16(vv.y - __bfloat162float(hy)));
        }
        __syncthreads();

        // ---- Scores: S = Q*K^T (3-pass split) ----
        float sc[8][4];
        #pragma unroll
        for (int nt = 0; nt < 8; nt++) {
            sc[nt][0] = sc[nt][1] = sc[nt][2] = sc[nt][3] = 0.0f;
            const int key = nt*8 + r0;
            #pragma unroll
            for (int kc = 0; kc < 4; kc++) {
                uint32_t bh0 = *(uint32_t*)&Kh[key*PADR + kc*16 + c0];
                uint32_t bh1 = *(uint32_t*)&Kh[key*PADR + kc*16 + c0 + 8];
                uint32_t bl0 = *(uint32_t*)&Kl[key*PADR + kc*16 + c0];
                uint32_t bl1 = *(uint32_t*)&Kl[key*PADR + kc*16 + c0 + 8];
                mma16816(sc[nt], aQh[kc], bh0, bh1);
                mma16816(sc[nt], aQh[kc], bl0, bl1);
                mma16816(sc[nt], aQl[kc], bh0, bh1);
            }
        }

        // ---- Online softmax (rows rA = qr, rB = qr+8) ----
        float mxA = -1e30f, mxB = -1e30f;
        #pragma unroll
        for (int nt = 0; nt < 8; nt++) {
            mxA = fmaxf(mxA, fmaxf(sc[nt][0], sc[nt][1]));
            mxB = fmaxf(mxB, fmaxf(sc[nt][2], sc[nt][3]));
        }
        mxA = fmaxf(mxA, __shfl_xor_sync(0xffffffff, mxA, 1));
        mxA = fmaxf(mxA, __shfl_xor_sync(0xffffffff, mxA, 2));
        mxB = fmaxf(mxB, __shfl_xor_sync(0xffffffff, mxB, 1));
        mxB = fmaxf(mxB, __shfl_xor_sync(0xffffffff, mxB, 2));

        float mnA = fmaxf(mA, mxA), mnB = fmaxf(mB, mxB);
        float alA = __expf(mA - mnA), alB = __expf(mB - mnB);
        float suA = 0.0f, suB = 0.0f;
        #pragma unroll
        for (int nt = 0; nt < 8; nt++) {
            sc[nt][0] = __expf(sc[nt][0] - mnA); suA += sc[nt][0];
            sc[nt][1] = __expf(sc[nt][1] - mnA); suA += sc[nt][1];
            sc[nt][2] = __expf(sc[nt][2] - mnB); suB += sc[nt][2];
            sc[nt][3] = __expf(sc[nt][3] - mnB); suB += sc[nt][3];
        }
        suA += __shfl_xor_sync(0xffffffff, suA, 1);
        suA += __shfl_xor_sync(0xffffffff, suA, 2);
        suB += __shfl_xor_sync(0xffffffff, suB, 1);
        suB += __shfl_xor_sync(0xffffffff, suB, 2);
        lA = lA * alA + suA;  mA = mnA;
        lB = lB * alB + suB;  mB = mnB;

        // ---- Rescale O, repack P (C-frag layout == A-frag layout) ----
        #pragma unroll
        for (int dt = 0; dt < 8; dt++) {
            o[dt][0] *= alA; o[dt][1] *= alA;
            o[dt][2] *= alB; o[dt][3] *= alB;
        }
        uint32_t aPh[4][4], aPl[4][4];
        #pragma unroll
        for (int kc = 0; kc < 4; kc++) {
            split2(make_float2(sc[2*kc  ][0], sc[2*kc  ][1]), aPh[kc][0], aPl[kc][0]);
            split2(make_float2(sc[2*kc  ][2], sc[2*kc  ][3]), aPh[kc][1], aPl[kc][1]);
            split2(make_float2(sc[2*kc+1][0], sc[2*kc+1][1]), aPh[kc][2], aPl[kc][2]);
            split2(make_float2(sc[2*kc+1][2], sc[2*kc+1][3]), aPh[kc][3], aPl[kc][3]);
        }

        // ---- O += P*V (3-pass split), V read from transposed smem ----
        const int nrow = r0;   // dim row within tile = dt*8 + r0
        #pragma unroll
        for (int dt = 0; dt < 8; dt++) {
            const int dim = dt*8 + nrow;
            const int sw  = (dim & 3) << 4;
            #pragma unroll
            for (int kc = 0; kc < 4; kc++) {
                uint32_t bh0 = *(uint32_t*)&Vh[dim*PADR + ((kc*16 + c0    ) ^ sw)];
                uint32_t bh1 = *(uint32_t*)&Vh[dim*PADR + ((kc*16 + c0 + 8) ^ sw)];
                uint32_t bl0 = *(uint32_t*)&Vl[dim*PADR + ((kc*16 + c0    ) ^ sw)];
                uint32_t bl1 = *(uint32_t*)&Vl[dim*PADR + ((kc*16 + c0 + 8) ^ sw)];
                mma16816(o[dt], aPh[kc], bh0, bh1);
                mma16816(o[dt], aPh[kc], bl0, bl1);
                mma16816(o[dt], aPl[kc], bh0, bh1);
            }
        }
    }

    // ---- Epilogue: normalize and store ----
    const float ivA = 1.0f / lA, ivB = 1.0f / lB;
    #pragma unroll
    for (int dt = 0; dt < 8; dt++) {
        float2 t0 = make_float2(o[dt][0] * ivA, o[dt][1] * ivA);
        float2 t1 = make_float2(o[dt][2] * ivB, o[dt][3] * ivB);
        *(float2*)&out[((size_t)(b*SS + qr    ))*DD + hb + dt*8 + c0] = t0;
        *(float2*)&out[((size_t)(b*SS + qr + 8))*DD + hb + dt*8 + c0] = t1;
    }
}

// ===========================================================================
extern "C" void kernel_launch(void* const* d_in, const int* in_sizes, int n_in,
                              void* d_out, int out_size)
{
    const float* x  = (const float*)d_in[0];
    const float* Wq = (const float*)d_in[1];
    const float* bq = (const float*)d_in[2];
    const float* Wk = (const float*)d_in[3];
    const float* bk = (const float*)d_in[4];
    const float* Wv = (const float*)d_in[5];
    const float* bv = (const float*)d_in[6];
    float* out = (float*)d_out;

    dim3 g1(DD / BN, MTOT / BM, 3);
    qkv_gemm_kernel<<<g1, 256>>>(x, Wq, bq, Wk, bk, Wv, bv);

    dim3 g2(SS / 64, HH, BB);
    attn_mma_kernel<<<g2, 128>>>(out);
}

// round 7
// speedup vs baseline: 2.3501x; 1.4638x over previous
#include <cuda_runtime.h>
#include <cuda_bf16.h>
#include <cstdint>

// Problem constants
#define BB 4
#define SS 2048
#define DD 512
#define HH 8
#define HDIM 64
#define MTOT (BB*SS)          // 8192 rows

// Scratch: pre-split bf16 (packed hi/lo pairs) + fp32 V for transpose
__device__ uint32_t gq_h[MTOT*DD/2];
__device__ uint32_t gq_l[MTOT*DD/2];
__device__ uint32_t gk_h[MTOT*DD/2];
__device__ uint32_t gk_l[MTOT*DD/2];
__device__ float    g_v [MTOT*DD];
__device__ uint32_t gvt_h[BB*HH*HDIM*(SS/2)];   // V^T [bh][dim][token-pair]
__device__ uint32_t gvt_l[BB*HH*HDIM*(SS/2)];

// ===========================================================================
// Helpers
// ===========================================================================
__device__ __forceinline__ uint32_t pack_bf16(__nv_bfloat16 x, __nv_bfloat16 y) {
    return (uint32_t)__bfloat16_as_ushort(x) | ((uint32_t)__bfloat16_as_ushort(y) << 16);
}
__device__ __forceinline__ void split2(float2 v, uint32_t& hi, uint32_t& lo) {
    __nv_bfloat16 hx = __float2bfloat16(v.x), hy = __float2bfloat16(v.y);
    float rx = v.x - __bfloat162float(hx);
    float ry = v.y - __bfloat162float(hy);
    hi = pack_bf16(hx, hy);
    lo = pack_bf16(__float2bfloat16(rx), __float2bfloat16(ry));
}
__device__ __forceinline__ void mma16816(float c[4], const uint32_t a[4],
                                         uint32_t b0, uint32_t b1) {
    asm volatile(
        "mma.sync.aligned.m16n8k16.row.col.f32.bf16.bf16.f32 "
        "{%0,%1,%2,%3}, {%4,%5,%6,%7}, {%8,%9}, {%0,%1,%2,%3};"
        : "+f"(c[0]), "+f"(c[1]), "+f"(c[2]), "+f"(c[3])
        : "r"(a[0]), "r"(a[1]), "r"(a[2]), "r"(a[3]), "r"(b0), "r"(b1));
}
#define LDSM4(R0,R1,R2,R3,ADDR) \
    asm volatile("ldmatrix.sync.aligned.m8n8.x4.shared.b16 {%0,%1,%2,%3}, [%4];" \
        : "=r"(R0),"=r"(R1),"=r"(R2),"=r"(R3) : "r"(ADDR))
#define CP_ASYNC16(DST, SRC) \
    asm volatile("cp.async.cg.shared.global [%0], [%1], 16;" :: "r"(DST), "l"(SRC))
#define CP_COMMIT() asm volatile("cp.async.commit_group;")

// ===========================================================================
// Kernel A: QKV GEMM. z=0 -> split Q (x0.125), z=1 -> split K, z=2 -> fp32 V
// ===========================================================================
#define BM 128
#define BN 128
#define BK 16

__global__ __launch_bounds__(256) void qkv_gemm_kernel(
    const float* __restrict__ x,
    const float* __restrict__ Wq, const float* __restrict__ bq,
    const float* __restrict__ Wk, const float* __restrict__ bk,
    const float* __restrict__ Wv, const float* __restrict__ bv)
{
    const float* W;
    const float* bias;
    if (blockIdx.z == 0)      { W = Wq; bias = bq; }
    else if (blockIdx.z == 1) { W = Wk; bias = bk; }
    else                      { W = Wv; bias = bv; }

    __shared__ float As[BK][BM];
    __shared__ float Bs[BK][BN];

    const int tid = threadIdx.x;
    const int tx = tid & 15;
    const int ty = tid >> 4;
    const int rowBase = blockIdx.y * BM;
    const int colBase = blockIdx.x * BN;

    float acc[8][8];
    #pragma unroll
    for (int i = 0; i < 8; i++)
        #pragma unroll
        for (int j = 0; j < 8; j++) acc[i][j] = 0.0f;

    for (int k0 = 0; k0 < DD; k0 += BK) {
        #pragma unroll
        for (int i = 0; i < 2; i++) {
            int f4 = tid + i * 256;
            int r  = f4 >> 2;
            int c4 = f4 & 3;
            float4 a = *(const float4*)&x[(size_t)(rowBase + r) * DD + k0 + c4 * 4];
            As[c4*4+0][r] = a.x; As[c4*4+1][r] = a.y;
            As[c4*4+2][r] = a.z; As[c4*4+3][r] = a.w;
            float4 w = *(const float4*)&W[(size_t)(colBase + r) * DD + k0 + c4 * 4];
            Bs[c4*4+0][r] = w.x; Bs[c4*4+1][r] = w.y;
            Bs[c4*4+2][r] = w.z; Bs[c4*4+3][r] = w.w;
        }
        __syncthreads();

        #pragma unroll
        for (int kk = 0; kk < BK; kk++) {
            float4 a0 = *(const float4*)&As[kk][ty * 8];
            float4 a1 = *(const float4*)&As[kk][ty * 8 + 4];
            float4 b0 = *(const float4*)&Bs[kk][tx * 8];
            float4 b1 = *(const float4*)&Bs[kk][tx * 8 + 4];
            float ar[8] = {a0.x, a0.y, a0.z, a0.w, a1.x, a1.y, a1.z, a1.w};
            float br[8] = {b0.x, b0.y, b0.z, b0.w, b1.x, b1.y, b1.z, b1.w};
            #pragma unroll
            for (int i = 0; i < 8; i++)
                #pragma unroll
                for (int j = 0; j < 8; j++)
                    acc[i][j] = fmaf(ar[i], br[j], acc[i][j]);
        }
        __syncthreads();
    }

    const int colLo = colBase + tx * 8;
    float4 bv0 = *(const float4*)&bias[colLo];
    float4 bv1 = *(const float4*)&bias[colLo + 4];
    float vb[8] = {bv0.x, bv0.y, bv0.z, bv0.w, bv1.x, bv1.y, bv1.z, bv1.w};

    if (blockIdx.z == 2) {
        #pragma unroll
        for (int i = 0; i < 8; i++) {
            int row = rowBase + ty * 8 + i;
            float4 o0, o1;
            o0.x = acc[i][0] + vb[0]; o0.y = acc[i][1] + vb[1];
            o0.z = acc[i][2] + vb[2]; o0.w = acc[i][3] + vb[3];
            o1.x = acc[i][4] + vb[4]; o1.y = acc[i][5] + vb[5];
            o1.z = acc[i][6] + vb[6]; o1.w = acc[i][7] + vb[7];
            *(float4*)&g_v[(size_t)row * DD + colLo]     = o0;
            *(float4*)&g_v[(size_t)row * DD + colLo + 4] = o1;
        }
    } else {
        const float scale = (blockIdx.z == 0) ? 0.125f : 1.0f;
        uint32_t* oh = (blockIdx.z == 0) ? gq_h : gk_h;
        uint32_t* ol = (blockIdx.z == 0) ? gq_l : gk_l;
        #pragma unroll
        for (int i = 0; i < 8; i++) {
            int row = rowBase + ty * 8 + i;
            uint32_t ph[4], pl[4];
            #pragma unroll
            for (int j = 0; j < 4; j++) {
                float2 v = make_float2((acc[i][2*j] + vb[2*j]) * scale,
                                       (acc[i][2*j+1] + vb[2*j+1]) * scale);
                split2(v, ph[j], pl[j]);
            }
            size_t base = (size_t)row * 256 + colLo / 2;
            *(uint2*)&oh[base]     = make_uint2(ph[0], ph[1]);
            *(uint2*)&oh[base + 2] = make_uint2(ph[2], ph[3]);
            *(uint2*)&ol[base]     = make_uint2(pl[0], pl[1]);
            *(uint2*)&ol[base + 2] = make_uint2(pl[2], pl[3]);
        }
    }
}

// ===========================================================================
// Kernel A2: split + transpose V -> gvt_h/gvt_l [bh][dim][token-pair]
// grid (SS/32, HDIM/32, BB*HH), block (32, 8)
// ===========================================================================
__global__ __launch_bounds__(256) void v_split_transpose_kernel()
{
    __shared__ float tile[32][33];
    const int bh = blockIdx.z;
    const int b = bh / HH, h = bh % HH;
    const int tok0 = blockIdx.x * 32;
    const int dim0 = blockIdx.y * 32;
    const int tx = threadIdx.x, ty = threadIdx.y;

    #pragma unroll
    for (int j = 0; j < 4; j++) {
        int tr = ty + 8 * j;
        tile[tr][tx] = g_v[(size_t)(b * SS + tok0 + tr) * DD + h * HDIM + dim0 + tx];
    }
    __syncthreads();
    #pragma unroll
    for (int it = 0; it < 2; it++) {
        int p  = (ty * 32 + tx) + it * 256;   // 0..511
        int dl = p >> 4;                       // local dim 0..31
        int pp = p & 15;                       // token pair 0..15
        uint32_t hi, lo;
        split2(make_float2(tile[2*pp][dl], tile[2*pp+1][dl]), hi, lo);
        size_t idx = (size_t)(bh * HDIM + dim0 + dl) * (SS/2) + (tok0 >> 1) + pp;
        gvt_h[idx] = hi;
        gvt_l[idx] = lo;
    }
}

// ===========================================================================
// Kernel B: warp-MMA flash attention. Pre-split operands, ldmatrix fragments,
// cp.async double-buffered staging.
// grid (S/64, H, B), 128 threads; warp w owns query rows [w*16, w*16+16).
// smem: K hi/lo [64 keys][128B], V^T hi/lo [64 dims][128B], XOR-swizzled,
// double buffered -> 64 KB dynamic.
// ===========================================================================
#define KT 64
#define NT (SS / KT)

__global__ __launch_bounds__(128) void attn_mma_kernel(float* __restrict__ out)
{
    extern __shared__ uint8_t dynsmem[];
    const int tid  = threadIdx.x;
    const int w    = tid >> 5;
    const int lane = tid & 31;
    const int r0   = lane >> 2;
    const int c0   = (lane & 3) * 2;
    const int qt = blockIdx.x, h = blockIdx.y, b = blockIdx.z;
    const int bh = b * HH + h;
    const int qr = qt * 64 + w * 16 + r0;

    const uint32_t smem_base = (uint32_t)__cvta_generic_to_shared(dynsmem);
    // layout: K(buf,arr) at (buf*2+arr)*8192 ; V(buf,arr) at 32768 + (buf*2+arr)*8192

    // ---- Q fragments straight from pre-split global ----
    uint32_t aQh[4][4], aQl[4][4];
    {
        const size_t row0 = (size_t)(b * SS + qr) * 256 + h * 32;
        const size_t row8 = row0 + 8 * 256;
        #pragma unroll
        for (int kc = 0; kc < 4; kc++) {
            int idx = kc * 8 + (lane & 3);
            aQh[kc][0] = gq_h[row0 + idx];     aQl[kc][0] = gq_l[row0 + idx];
            aQh[kc][1] = gq_h[row8 + idx];     aQl[kc][1] = gq_l[row8 + idx];
            aQh[kc][2] = gq_h[row0 + idx + 4]; aQl[kc][2] = gq_l[row0 + idx + 4];
            aQh[kc][3] = gq_h[row8 + idx + 4]; aQl[kc][3] = gq_l[row8 + idx + 4];
        }
    }

    // ---- cp.async staging: 16 x 16B chunks per thread per tile ----
    auto stage = [&](int buf, int t) {
        #pragma unroll
        for (int j = 0; j < 16; j++) {
            const int c = tid + (j & 3) * 128;   // 0..511 within array
            const int arr4 = j >> 2;             // 0:Kh 1:Kl 2:Vh 3:Vl
            const int r = c >> 3, i = c & 7;
            const uint32_t swz = (uint32_t)((i * 16) ^ ((r & 7) << 4));
            const uint32_t* src;
            uint32_t dst;
            if (arr4 < 2) {
                src = (arr4 == 0 ? gk_h : gk_l) +
                      ((size_t)(b * SS + t * KT + r) * 256 + h * 32 + i * 4);
                dst = smem_base + (uint32_t)((buf * 2 + arr4) * 8192 + r * 128) + swz;
            } else {
                src = (arr4 == 2 ? gvt_h : gvt_l) +
                      ((size_t)(bh * HDIM + r) * (SS/2) + t * 32 + i * 4);
                dst = smem_base + 32768u + (uint32_t)((buf * 2 + (arr4 - 2)) * 8192 + r * 128) + swz;
            }
            CP_ASYNC16(dst, src);
        }
    };

    float o[8][4];
    #pragma unroll
    for (int dt = 0; dt < 8; dt++)
        #pragma unroll
        for (int i = 0; i < 4; i++) o[dt][i] = 0.0f;
    float mA = -1e30f, mB = -1e30f, lA = 0.0f, lB = 0.0f;

    // per-thread ldmatrix row parameters (same for K keys and V dims)
    const int lrow = ((lane >> 4) << 3) + (lane & 7);   // matrix row within group-pair
    const int osel = (lane >> 3) & 1;                   // oct parity (b0 vs b1)
    const uint32_t lswz = (uint32_t)((lrow & 7) << 4);

    stage(0, 0);
    CP_COMMIT();

    for (int t = 0; t < NT; t++) {
        const int buf = t & 1;
        if (t + 1 < NT) {
            stage(buf ^ 1, t + 1);
            CP_COMMIT();
            asm volatile("cp.async.wait_group 1;");
        } else {
            asm volatile("cp.async.wait_group 0;");
        }
        __syncthreads();

        const uint32_t Kh_b = smem_base + (uint32_t)((buf * 2 + 0) * 8192);
        const uint32_t Kl_b = smem_base + (uint32_t)((buf * 2 + 1) * 8192);
        const uint32_t Vh_b = smem_base + 32768u + (uint32_t)((buf * 2 + 0) * 8192);
        const uint32_t Vl_b = smem_base + 32768u + (uint32_t)((buf * 2 + 1) * 8192);

        // ---- Scores: S = Q*K^T (split-bf16 3-pass), ldmatrix B-frags ----
        float sc[8][4];
        #pragma unroll
        for (int gp = 0; gp < 4; gp++) {
            float s0[4] = {0,0,0,0}, s1[4] = {0,0,0,0};
            const uint32_t rbase = (uint32_t)((gp * 16 + lrow) * 128);
            #pragma unroll
            for (int kc = 0; kc < 4; kc++) {
                const uint32_t boff = (uint32_t)(((2*kc + osel) * 16)) ^ lswz;
                uint32_t h0,h1,h2,h3, l0,l1,l2,l3;
                LDSM4(h0,h1,h2,h3, Kh_b + rbase + boff);
                LDSM4(l0,l1,l2,l3, Kl_b + rbase + boff);
                mma16816(s0, aQh[kc], h0, h1);
                mma16816(s0, aQh[kc], l0, l1);
                mma16816(s0, aQl[kc], h0, h1);
                mma16816(s1, aQh[kc], h2, h3);
                mma16816(s1, aQh[kc], l2, l3);
                mma16816(s1, aQl[kc], h2, h3);
            }
            #pragma unroll
            for (int i = 0; i < 4; i++) { sc[2*gp][i] = s0[i]; sc[2*gp+1][i] = s1[i]; }
        }

        // ---- Online softmax (rows qr and qr+8) ----
        float mxA = -1e30f, mxB = -1e30f;
        #pragma unroll
        for (int nt = 0; nt < 8; nt++) {
            mxA = fmaxf(mxA, fmaxf(sc[nt][0], sc[nt][1]));
            mxB = fmaxf(mxB, fmaxf(sc[nt][2], sc[nt][3]));
        }
        mxA = fmaxf(mxA, __shfl_xor_sync(0xffffffff, mxA, 1));
        mxA = fmaxf(mxA, __shfl_xor_sync(0xffffffff, mxA, 2));
        mxB = fmaxf(mxB, __shfl_xor_sync(0xffffffff, mxB, 1));
        mxB = fmaxf(mxB, __shfl_xor_sync(0xffffffff, mxB, 2));

        float mnA = fmaxf(mA, mxA), mnB = fmaxf(mB, mxB);
        float alA = __expf(mA - mnA), alB = __expf(mB - mnB);
        float suA = 0.0f, suB = 0.0f;
        #pragma unroll
        for (int nt = 0; nt < 8; nt++) {
            sc[nt][0] = __expf(sc[nt][0] - mnA); suA += sc[nt][0];
            sc[nt][1] = __expf(sc[nt][1] - mnA); suA += sc[nt][1];
            sc[nt][2] = __expf(sc[nt][2] - mnB); suB += sc[nt][2];
            sc[nt][3] = __expf(sc[nt][3] - mnB); suB += sc[nt][3];
        }
        suA += __shfl_xor_sync(0xffffffff, suA, 1);
        suA += __shfl_xor_sync(0xffffffff, suA, 2);
        suB += __shfl_xor_sync(0xffffffff, suB, 1);
        suB += __shfl_xor_sync(0xffffffff, suB, 2);
        lA = lA * alA + suA;  mA = mnA;
        lB = lB * alB + suB;  mB = mnB;

        // ---- Rescale O, repack P into A-fragments ----
        #pragma unroll
        for (int dt = 0; dt < 8; dt++) {
            o[dt][0] *= alA; o[dt][1] *= alA;
            o[dt][2] *= alB; o[dt][3] *= alB;
        }
        uint32_t aPh[4][4], aPl[4][4];
        #pragma unroll
        for (int kc = 0; kc < 4; kc++) {
            split2(make_float2(sc[2*kc  ][0], sc[2*kc  ][1]), aPh[kc][0], aPl[kc][0]);
            split2(make_float2(sc[2*kc  ][2], sc[2*kc  ][3]), aPh[kc][1], aPl[kc][1]);
            split2(make_float2(sc[2*kc+1][0], sc[2*kc+1][1]), aPh[kc][2], aPl[kc][2]);
            split2(make_float2(sc[2*kc+1][2], sc[2*kc+1][3]), aPh[kc][3], aPl[kc][3]);
        }

        // ---- O += P*V (split-bf16 3-pass), V^T from smem via ldmatrix ----
        #pragma unroll
        for (int dtp = 0; dtp < 4; dtp++) {
            const uint32_t rbase = (uint32_t)((dtp * 16 + lrow) * 128);
            #pragma unroll
            for (int kc = 0; kc < 4; kc++) {
                const uint32_t boff = (uint32_t)(((2*kc + osel) * 16)) ^ lswz;
                uint32_t v0,v1,v2,v3, w0,w1,w2,w3;
                LDSM4(v0,v1,v2,v3, Vh_b + rbase + boff);
                LDSM4(w0,w1,w2,w3, Vl_b + rbase + boff);
                mma16816(o[2*dtp],   aPh[kc], v0, v1);
                mma16816(o[2*dtp],   aPh[kc], w0, w1);
                mma16816(o[2*dtp],   aPl[kc], v0, v1);
                mma16816(o[2*dtp+1], aPh[kc], v2, v3);
                mma16816(o[2*dtp+1], aPh[kc], w2, w3);
                mma16816(o[2*dtp+1], aPl[kc], v2, v3);
            }
        }
        __syncthreads();   // all warps done with buf before it is restaged
    }

    // ---- Epilogue: normalize and store ----
    const float ivA = 1.0f / lA, ivB = 1.0f / lB;
    #pragma unroll
    for (int dt = 0; dt < 8; dt++) {
        float2 t0 = make_float2(o[dt][0] * ivA, o[dt][1] * ivA);
        float2 t1 = make_float2(o[dt][2] * ivB, o[dt][3] * ivB);
        *(float2*)&out[((size_t)(b*SS + qr    ))*DD + h*HDIM + dt*8 + c0] = t0;
        *(float2*)&out[((size_t)(b*SS + qr + 8))*DD + h*HDIM + dt*8 + c0] = t1;
    }
}

// ===========================================================================
extern "C" void kernel_launch(void* const* d_in, const int* in_sizes, int n_in,
                              void* d_out, int out_size)
{
    const float* x  = (const float*)d_in[0];
    const float* Wq = (const float*)d_in[1];
    const float* bq = (const float*)d_in[2];
    const float* Wk = (const float*)d_in[3];
    const float* bk = (const float*)d_in[4];
    const float* Wv = (const float*)d_in[5];
    const float* bv = (const float*)d_in[6];
    float* out = (float*)d_out;

    dim3 g1(DD / BN, MTOT / BM, 3);
    qkv_gemm_kernel<<<g1, 256>>>(x, Wq, bq, Wk, bk, Wv, bv);

    dim3 gt(SS / 32, HDIM / 32, BB * HH);
    v_split_transpose_kernel<<<gt, dim3(32, 8)>>>();

    // Unconditional every call (no static guards). Idempotent.
    cudaFuncSetAttribute(attn_mma_kernel,
                         cudaFuncAttributeMaxDynamicSharedMemorySize, 65536);
    dim3 g2(SS / 64, HH, BB);
    attn_mma_kernel<<<g2, 128, 65536>>>(out);
}

// round 8
// speedup vs baseline: 3.7670x; 1.6029x over previous
#include <cuda_runtime.h>
#include <cuda_bf16.h>
#include <cstdint>

// Problem constants
#define BB 4
#define SS 2048
#define DD 512
#define HH 8
#define HDIM 64
#define MTOT (BB*SS)          // 8192 rows

// Pre-split operands (packed bf16 hi/lo pairs as uint32)
__device__ uint32_t gx_h[MTOT*DD/2];           // x split
__device__ uint32_t gx_l[MTOT*DD/2];
__device__ uint32_t gw_h[3*DD*DD/2];           // Wq/Wk/Wv split
__device__ uint32_t gw_l[3*DD*DD/2];
__device__ uint32_t gq_h[MTOT*DD/2];           // projected q/k split
__device__ uint32_t gq_l[MTOT*DD/2];
__device__ uint32_t gk_h[MTOT*DD/2];
__device__ uint32_t gk_l[MTOT*DD/2];
__device__ float    g_v [MTOT*DD];             // projected v fp32
__device__ uint32_t gvt_h[BB*HH*HDIM*(SS/2)];  // V^T split [bh][dim][tok-pair]
__device__ uint32_t gvt_l[BB*HH*HDIM*(SS/2)];

// ===========================================================================
// Helpers
// ===========================================================================
__device__ __forceinline__ uint32_t pack_bf16(__nv_bfloat16 x, __nv_bfloat16 y) {
    return (uint32_t)__bfloat16_as_ushort(x) | ((uint32_t)__bfloat16_as_ushort(y) << 16);
}
__device__ __forceinline__ void split2(float2 v, uint32_t& hi, uint32_t& lo) {
    __nv_bfloat16 hx = __float2bfloat16(v.x), hy = __float2bfloat16(v.y);
    float rx = v.x - __bfloat162float(hx);
    float ry = v.y - __bfloat162float(hy);
    hi = pack_bf16(hx, hy);
    lo = pack_bf16(__float2bfloat16(rx), __float2bfloat16(ry));
}
__device__ __forceinline__ void mma16816(float c[4], const uint32_t a[4],
                                         uint32_t b0, uint32_t b1) {
    asm volatile(
        "mma.sync.aligned.m16n8k16.row.col.f32.bf16.bf16.f32 "
        "{%0,%1,%2,%3}, {%4,%5,%6,%7}, {%8,%9}, {%0,%1,%2,%3};"
        : "+f"(c[0]), "+f"(c[1]), "+f"(c[2]), "+f"(c[3])
        : "r"(a[0]), "r"(a[1]), "r"(a[2]), "r"(a[3]), "r"(b0), "r"(b1));
}
#define LDSM4(R0,R1,R2,R3,ADDR) \
    asm volatile("ldmatrix.sync.aligned.m8n8.x4.shared.b16 {%0,%1,%2,%3}, [%4];" \
        : "=r"(R0),"=r"(R1),"=r"(R2),"=r"(R3) : "r"(ADDR))
#define CP_ASYNC16(DST, SRC) \
    asm volatile("cp.async.cg.shared.global [%0], [%1], 16;" :: "r"(DST), "l"(SRC))
#define CP_COMMIT() asm volatile("cp.async.commit_group;")

// ===========================================================================
// Kernel 0a/0b: pre-split x and W into packed bf16 hi/lo pairs
// ===========================================================================
__global__ __launch_bounds__(256) void split_x_kernel(const float* __restrict__ x)
{
    int idx = blockIdx.x * 256 + threadIdx.x;      // pair index, total 2M
    float2 v = *(const float2*)&x[(size_t)idx * 2];
    split2(v, gx_h[idx], gx_l[idx]);
}
__global__ __launch_bounds__(256) void split_w_kernel(
    const float* __restrict__ Wq, const float* __restrict__ Wk,
    const float* __restrict__ Wv)
{
    const float* W = (blockIdx.y == 0) ? Wq : (blockIdx.y == 1) ? Wk : Wv;
    int idx = blockIdx.x * 256 + threadIdx.x;      // pair index within W (131072)
    float2 v = *(const float2*)&W[(size_t)idx * 2];
    size_t o = (size_t)blockIdx.y * (DD * DD / 2) + idx;
    split2(v, gw_h[o], gw_l[o]);
}

// ===========================================================================
// Kernel A: QKV GEMM on warp MMA, split-bf16 3-pass.
// C[M=8192, N=512] = x @ W^T (+bias in epilogue). z selects q/k/v.
// Tiles: BM=128, BN=64, BK=64. 256 thr = 8 warps (4 m x 2 n), warp 32x32.
// smem per buffer: A hi/lo 2x16KB + B hi/lo 2x8KB = 48KB; double buffer 96KB.
// ===========================================================================
#define GBM 128
#define GBN 64
#define GBK 64

__global__ __launch_bounds__(256) void qkv_mma_gemm_kernel(
    const float* __restrict__ bq, const float* __restrict__ bk,
    const float* __restrict__ bv)
{
    extern __shared__ uint8_t gsm[];
    const uint32_t sb = (uint32_t)__cvta_generic_to_shared(gsm);
    const int tid = threadIdx.x;
    const int wid = tid >> 5, lane = tid & 31;
    const int sel = blockIdx.z;
    const int nBase = blockIdx.x * GBN;
    const int mBase = blockIdx.y * GBM;
    const int m0 = (wid >> 1) * 32;
    const int n0 = (wid & 1) * 32;

    const uint32_t* WH = gw_h + (size_t)sel * (DD * DD / 2);
    const uint32_t* WL = gw_l + (size_t)sel * (DD * DD / 2);
    const float* bias = (sel == 0) ? bq : (sel == 1) ? bk : bv;

    // cp.async staging: per k-iter stage A (2048 16B chunks) + B (1024)
    auto stage = [&](int buf, int kk) {
        const uint32_t bufo = (uint32_t)(buf * 49152);
        #pragma unroll
        for (int j = 0; j < 8; j++) {                 // A
            int c = tid + j * 256;
            int arr = c >> 10, wi = c & 1023;
            int r = wi >> 3, i = wi & 7;
            uint32_t dst = sb + bufo + (uint32_t)(arr * 16384 + r * 128)
                           + (uint32_t)((i * 16) ^ ((r & 7) << 4));
            const uint32_t* src = (arr == 0 ? gx_h : gx_l)
                                  + ((size_t)(mBase + r) * 256 + kk * 32 + i * 4);
            CP_ASYNC16(dst, src);
        }
        #pragma unroll
        for (int j = 0; j < 4; j++) {                 // B
            int c = tid + j * 256;
            int arr = c >> 9, wi = c & 511;
            int r = wi >> 3, i = wi & 7;
            uint32_t dst = sb + bufo + 32768u + (uint32_t)(arr * 8192 + r * 128)
                           + (uint32_t)((i * 16) ^ ((r & 7) << 4));
            const uint32_t* src = (arr == 0 ? WH : WL)
                                  + ((size_t)(nBase + r) * 256 + kk * 32 + i * 4);
            CP_ASYNC16(dst, src);
        }
    };

    float c[2][4][4];
    #pragma unroll
    for (int mt = 0; mt < 2; mt++)
        #pragma unroll
        for (int t = 0; t < 4; t++)
            #pragma unroll
            for (int i = 0; i < 4; i++) c[mt][t][i] = 0.0f;

    // ldmatrix lane mappings
    const int arow  = (((lane >> 3) & 1) << 3) | (lane & 7);  // A (row-major a-frag)
    const int ahalf = lane >> 4;
    const uint32_t aswz = (uint32_t)((arow & 7) << 4);
    const int brow  = ((lane >> 4) << 3) | (lane & 7);        // B (n-major b-frag)
    const int bosel = (lane >> 3) & 1;
    const uint32_t bswz = (uint32_t)((brow & 7) << 4);

    stage(0, 0);
    CP_COMMIT();

    #pragma unroll 1
    for (int kk = 0; kk < DD / GBK; kk++) {
        const int buf = kk & 1;
        if (kk + 1 < DD / GBK) {
            stage(buf ^ 1, kk + 1);
            CP_COMMIT();
            asm volatile("cp.async.wait_group 1;");
        } else {
            asm volatile("cp.async.wait_group 0;");
        }
        __syncthreads();

        const uint32_t Ah = sb + (uint32_t)(buf * 49152);
        const uint32_t Al = Ah + 16384u;
        const uint32_t Bh = Ah + 32768u;
        const uint32_t Bl = Bh + 8192u;

        #pragma unroll
        for (int kc = 0; kc < 4; kc++) {
            const uint32_t acol = (uint32_t)(((2 * kc + ahalf) * 16)) ^ aswz;
            const uint32_t bcol = (uint32_t)(((2 * kc + bosel) * 16)) ^ bswz;
            uint32_t ah[2][4], al[2][4], bh[2][4], bl[2][4];
            #pragma unroll
            for (int mt = 0; mt < 2; mt++) {
                uint32_t ro = (uint32_t)((m0 + mt * 16 + arow) * 128);
                LDSM4(ah[mt][0], ah[mt][1], ah[mt][2], ah[mt][3], Ah + ro + acol);
                LDSM4(al[mt][0], al[mt][1], al[mt][2], al[mt][3], Al + ro + acol);
            }
            #pragma unroll
            for (int gp = 0; gp < 2; gp++) {
                uint32_t ro = (uint32_t)((n0 + gp * 16 + brow) * 128);
                LDSM4(bh[gp][0], bh[gp][1], bh[gp][2], bh[gp][3], Bh + ro + bcol);
                LDSM4(bl[gp][0], bl[gp][1], bl[gp][2], bl[gp][3], Bl + ro + bcol);
            }
            #pragma unroll
            for (int mt = 0; mt < 2; mt++)
                #pragma unroll
                for (int t = 0; t < 4; t++) {
                    const int gp = t >> 1, pv = (t & 1) * 2;
                    mma16816(c[mt][t], ah[mt], bh[gp][pv], bh[gp][pv + 1]);
                    mma16816(c[mt][t], ah[mt], bl[gp][pv], bl[gp][pv + 1]);
                    mma16816(c[mt][t], al[mt], bh[gp][pv], bh[gp][pv + 1]);
                }
        }
        __syncthreads();
    }

    // ---- Epilogue: bias, (scale for q), store split q/k or fp32 v ----
    const int crow = lane >> 2;
    const int ccol = (lane & 3) * 2;
    const float scale = (sel == 0) ? 0.125f : 1.0f;
    #pragma unroll
    for (int mt = 0; mt < 2; mt++)
        #pragma unroll
        for (int t = 0; t < 4; t++) {
            const int row = mBase + m0 + mt * 16 + crow;
            const int col = nBase + n0 + t * 8 + ccol;
            const float b0 = bias[col], b1 = bias[col + 1];
            float2 v0 = make_float2(c[mt][t][0] + b0, c[mt][t][1] + b1);
            float2 v1 = make_float2(c[mt][t][2] + b0, c[mt][t][3] + b1);
            if (sel == 2) {
                *(float2*)&g_v[(size_t)row * DD + col]       = v0;
                *(float2*)&g_v[(size_t)(row + 8) * DD + col] = v1;
            } else {
                v0.x *= scale; v0.y *= scale; v1.x *= scale; v1.y *= scale;
                uint32_t* oh = (sel == 0) ? gq_h : gk_h;
                uint32_t* ol = (sel == 0) ? gq_l : gk_l;
                size_t p0 = (size_t)row * 256 + col / 2;
                size_t p1 = (size_t)(row + 8) * 256 + col / 2;
                split2(v0, oh[p0], ol[p0]);
                split2(v1, oh[p1], ol[p1]);
            }
        }
}

// ===========================================================================
// Kernel A2: split + transpose V -> gvt_h/gvt_l [bh][dim][token-pair]
// ===========================================================================
__global__ __launch_bounds__(256) void v_split_transpose_kernel()
{
    __shared__ float tile[32][33];
    const int bh = blockIdx.z;
    const int b = bh / HH, h = bh % HH;
    const int tok0 = blockIdx.x * 32;
    const int dim0 = blockIdx.y * 32;
    const int tx = threadIdx.x, ty = threadIdx.y;

    #pragma unroll
    for (int j = 0; j < 4; j++) {
        int tr = ty + 8 * j;
        tile[tr][tx] = g_v[(size_t)(b * SS + tok0 + tr) * DD + h * HDIM + dim0 + tx];
    }
    __syncthreads();
    #pragma unroll
    for (int it = 0; it < 2; it++) {
        int p  = (ty * 32 + tx) + it * 256;
        int dl = p >> 4;
        int pp = p & 15;
        uint32_t hi, lo;
        split2(make_float2(tile[2*pp][dl], tile[2*pp+1][dl]), hi, lo);
        size_t idx = (size_t)(bh * HDIM + dim0 + dl) * (SS/2) + (tok0 >> 1) + pp;
        gvt_h[idx] = hi;
        gvt_l[idx] = lo;
    }
}

// ===========================================================================
// Kernel B: warp-MMA flash attention (unchanged from R7, validated)
// ===========================================================================
#define KT 64
#define NT (SS / KT)

__global__ __launch_bounds__(128) void attn_mma_kernel(float* __restrict__ out)
{
    extern __shared__ uint8_t dynsmem[];
    const int tid  = threadIdx.x;
    const int w    = tid >> 5;
    const int lane = tid & 31;
    const int r0   = lane >> 2;
    const int c0   = (lane & 3) * 2;
    const int qt = blockIdx.x, h = blockIdx.y, b = blockIdx.z;
    const int bh = b * HH + h;
    const int qr = qt * 64 + w * 16 + r0;

    const uint32_t smem_base = (uint32_t)__cvta_generic_to_shared(dynsmem);

    uint32_t aQh[4][4], aQl[4][4];
    {
        const size_t row0 = (size_t)(b * SS + qr) * 256 + h * 32;
        const size_t row8 = row0 + 8 * 256;
        #pragma unroll
        for (int kc = 0; kc < 4; kc++) {
            int idx = kc * 8 + (lane & 3);
            aQh[kc][0] = gq_h[row0 + idx];     aQl[kc][0] = gq_l[row0 + idx];
            aQh[kc][1] = gq_h[row8 + idx];     aQl[kc][1] = gq_l[row8 + idx];
            aQh[kc][2] = gq_h[row0 + idx + 4]; aQl[kc][2] = gq_l[row0 + idx + 4];
            aQh[kc][3] = gq_h[row8 + idx + 4]; aQl[kc][3] = gq_l[row8 + idx + 4];
        }
    }

    auto stage = [&](int buf, int t) {
        #pragma unroll
        for (int j = 0; j < 16; j++) {
            const int c = tid + (j & 3) * 128;
            const int arr4 = j >> 2;
            const int r = c >> 3, i = c & 7;
            const uint32_t swz = (uint32_t)((i * 16) ^ ((r & 7) << 4));
            const uint32_t* src;
            uint32_t dst;
            if (arr4 < 2) {
                src = (arr4 == 0 ? gk_h : gk_l) +
                      ((size_t)(b * SS + t * KT + r) * 256 + h * 32 + i * 4);
                dst = smem_base + (uint32_t)((buf * 2 + arr4) * 8192 + r * 128) + swz;
            } else {
                src = (arr4 == 2 ? gvt_h : gvt_l) +
                      ((size_t)(bh * HDIM + r) * (SS/2) + t * 32 + i * 4);
                dst = smem_base + 32768u + (uint32_t)((buf * 2 + (arr4 - 2)) * 8192 + r * 128) + swz;
            }
            CP_ASYNC16(dst, src);
        }
    };

    float o[8][4];
    #pragma unroll
    for (int dt = 0; dt < 8; dt++)
        #pragma unroll
        for (int i = 0; i < 4; i++) o[dt][i] = 0.0f;
    float mA = -1e30f, mB = -1e30f, lA = 0.0f, lB = 0.0f;

    const int lrow = ((lane >> 4) << 3) + (lane & 7);
    const int osel = (lane >> 3) & 1;
    const uint32_t lswz = (uint32_t)((lrow & 7) << 4);

    stage(0, 0);
    CP_COMMIT();

    for (int t = 0; t < NT; t++) {
        const int buf = t & 1;
        if (t + 1 < NT) {
            stage(buf ^ 1, t + 1);
            CP_COMMIT();
            asm volatile("cp.async.wait_group 1;");
        } else {
            asm volatile("cp.async.wait_group 0;");
        }
        __syncthreads();

        const uint32_t Kh_b = smem_base + (uint32_t)((buf * 2 + 0) * 8192);
        const uint32_t Kl_b = smem_base + (uint32_t)((buf * 2 + 1) * 8192);
        const uint32_t Vh_b = smem_base + 32768u + (uint32_t)((buf * 2 + 0) * 8192);
        const uint32_t Vl_b = smem_base + 32768u + (uint32_t)((buf * 2 + 1) * 8192);

        float sc[8][4];
        #pragma unroll
        for (int gp = 0; gp < 4; gp++) {
            float s0[4] = {0,0,0,0}, s1[4] = {0,0,0,0};
            const uint32_t rbase = (uint32_t)((gp * 16 + lrow) * 128);
            #pragma unroll
            for (int kc = 0; kc < 4; kc++) {
                const uint32_t boff = (uint32_t)(((2*kc + osel) * 16)) ^ lswz;
                uint32_t h0,h1,h2,h3, l0,l1,l2,l3;
                LDSM4(h0,h1,h2,h3, Kh_b + rbase + boff);
                LDSM4(l0,l1,l2,l3, Kl_b + rbase + boff);
                mma16816(s0, aQh[kc], h0, h1);
                mma16816(s0, aQh[kc], l0, l1);
                mma16816(s0, aQl[kc], h0, h1);
                mma16816(s1, aQh[kc], h2, h3);
                mma16816(s1, aQh[kc], l2, l3);
                mma16816(s1, aQl[kc], h2, h3);
            }
            #pragma unroll
            for (int i = 0; i < 4; i++) { sc[2*gp][i] = s0[i]; sc[2*gp+1][i] = s1[i]; }
        }

        float mxA = -1e30f, mxB = -1e30f;
        #pragma unroll
        for (int nt = 0; nt < 8; nt++) {
            mxA = fmaxf(mxA, fmaxf(sc[nt][0], sc[nt][1]));
            mxB = fmaxf(mxB, fmaxf(sc[nt][2], sc[nt][3]));
        }
        mxA = fmaxf(mxA, __shfl_xor_sync(0xffffffff, mxA, 1));
        mxA = fmaxf(mxA, __shfl_xor_sync(0xffffffff, mxA, 2));
        mxB = fmaxf(mxB, __shfl_xor_sync(0xffffffff, mxB, 1));
        mxB = fmaxf(mxB, __shfl_xor_sync(0xffffffff, mxB, 2));

        float mnA = fmaxf(mA, mxA), mnB = fmaxf(mB, mxB);
        float alA = __expf(mA - mnA), alB = __expf(mB - mnB);
        float suA = 0.0f, suB = 0.0f;
        #pragma unroll
        for (int nt = 0; nt < 8; nt++) {
            sc[nt][0] = __expf(sc[nt][0] - mnA); suA += sc[nt][0];
            sc[nt][1] = __expf(sc[nt][1] - mnA); suA += sc[nt][1];
            sc[nt][2] = __expf(sc[nt][2] - mnB); suB += sc[nt][2];
            sc[nt][3] = __expf(sc[nt][3] - mnB); suB += sc[nt][3];
        }
        suA += __shfl_xor_sync(0xffffffff, suA, 1);
        suA += __shfl_xor_sync(0xffffffff, suA, 2);
        suB += __shfl_xor_sync(0xffffffff, suB, 1);
        suB += __shfl_xor_sync(0xffffffff, suB, 2);
        lA = lA * alA + suA;  mA = mnA;
        lB = lB * alB + suB;  mB = mnB;

        #pragma unroll
        for (int dt = 0; dt < 8; dt++) {
            o[dt][0] *= alA; o[dt][1] *= alA;
            o[dt][2] *= alB; o[dt][3] *= alB;
        }
        uint32_t aPh[4][4], aPl[4][4];
        #pragma unroll
        for (int kc = 0; kc < 4; kc++) {
            split2(make_float2(sc[2*kc  ][0], sc[2*kc  ][1]), aPh[kc][0], aPl[kc][0]);
            split2(make_float2(sc[2*kc  ][2], sc[2*kc  ][3]), aPh[kc][1], aPl[kc][1]);
            split2(make_float2(sc[2*kc+1][0], sc[2*kc+1][1]), aPh[kc][2], aPl[kc][2]);
            split2(make_float2(sc[2*kc+1][2], sc[2*kc+1][3]), aPh[kc][3], aPl[kc][3]);
        }

        #pragma unroll
        for (int dtp = 0; dtp < 4; dtp++) {
            const uint32_t rbase = (uint32_t)((dtp * 16 + lrow) * 128);
            #pragma unroll
            for (int kc = 0; kc < 4; kc++) {
                const uint32_t boff = (uint32_t)(((2*kc + osel) * 16)) ^ lswz;
                uint32_t v0,v1,v2,v3, w0,w1,w2,w3;
                LDSM4(v0,v1,v2,v3, Vh_b + rbase + boff);
                LDSM4(w0,w1,w2,w3, Vl_b + rbase + boff);
                mma16816(o[2*dtp],   aPh[kc], v0, v1);
                mma16816(o[2*dtp],   aPh[kc], w0, w1);
                mma16816(o[2*dtp],   aPl[kc], v0, v1);
                mma16816(o[2*dtp+1], aPh[kc], v2, v3);
                mma16816(o[2*dtp+1], aPh[kc], w2, w3);
                mma16816(o[2*dtp+1], aPl[kc], v2, v3);
            }
        }
        __syncthreads();
    }

    const float ivA = 1.0f / lA, ivB = 1.0f / lB;
    #pragma unroll
    for (int dt = 0; dt < 8; dt++) {
        float2 t0 = make_float2(o[dt][0] * ivA, o[dt][1] * ivA);
        float2 t1 = make_float2(o[dt][2] * ivB, o[dt][3] * ivB);
        *(float2*)&out[((size_t)(b*SS + qr    ))*DD + h*HDIM + dt*8 + c0] = t0;
        *(float2*)&out[((size_t)(b*SS + qr + 8))*DD + h*HDIM + dt*8 + c0] = t1;
    }
}

// ===========================================================================
extern "C" void kernel_launch(void* const* d_in, const int* in_sizes, int n_in,
                              void* d_out, int out_size)
{
    const float* x  = (const float*)d_in[0];
    const float* Wq = (const float*)d_in[1];
    const float* bq = (const float*)d_in[2];
    const float* Wk = (const float*)d_in[3];
    const float* bk = (const float*)d_in[4];
    const float* Wv = (const float*)d_in[5];
    const float* bv = (const float*)d_in[6];
    float* out = (float*)d_out;

    split_x_kernel<<<MTOT * DD / 2 / 256, 256>>>(x);
    split_w_kernel<<<dim3(DD * DD / 2 / 256, 3), 256>>>(Wq, Wk, Wv);

    cudaFuncSetAttribute(qkv_mma_gemm_kernel,
                         cudaFuncAttributeMaxDynamicSharedMemorySize, 98304);
    dim3 gg(DD / GBN, MTOT / GBM, 3);
    qkv_mma_gemm_kernel<<<gg, 256, 98304>>>(bq, bk, bv);

    dim3 gt(SS / 32, HDIM / 32, BB * HH);
    v_split_transpose_kernel<<<gt, dim3(32, 8)>>>();

    cudaFuncSetAttribute(attn_mma_kernel,
                         cudaFuncAttributeMaxDynamicSharedMemorySize, 65536);
    dim3 g2(SS / 64, HH, BB);
    attn_mma_kernel<<<g2, 128, 65536>>>(out);
}